// round 15
// baseline (speedup 1.0000x reference)
#include <cuda_runtime.h>
#include <cstdint>
#include <float.h>

#define FIN  128
#define FOUT 64
#define NEG  0.2f
#define NMAX 50048
#define EMAX 1000192

#define PADK 132   // smem row stride (floats) for xs / wsT
#define PADS 68    // smem row stride for output staging

// packed fp32 FMA (Blackwell FFMA2): d = a*b + c elementwise on 2 packed f32
#define FMA_F32X2(d, a, b, c) \
    asm("fma.rn.f32x2 %0, %1, %2, %3;" : "=l"(d) : "l"(a), "l"(b), "l"(c))

// ---------------- scratch (device globals; zero-initialized at load) --------
// Invariant: deg[], cursor[] are zero at entry; restored by gather epilogue.
__device__ float    g_Wh[NMAX * FOUT];
__device__ float    g_ssrc[NMAX];
__device__ float    g_sdst[NMAX];
__device__ int      g_deg[NMAX];
__device__ int      g_cursor[NMAX];
__device__ int      g_rowstart[NMAX];
__device__ uint2    g_bkt[EMAX];          // (src, bitcast(e)) bucketed by dst
__device__ int      g_total;              // bump allocator

// ---------------- per-block edge-dtype detect --------------------------------
__device__ __forceinline__ int detect_is64(const unsigned* eiw) {
    unsigned v = 0;
    if (threadIdx.x < 64) v = eiw[threadIdx.x * 2 + 1];
    return __syncthreads_or(v != 0u) ? 0 : 1;
}

__device__ __forceinline__ void load_edge(const void* ei, int is64, int E,
                                          int i, int N, int& s, int& d) {
    if (is64) {
        const long long* p = (const long long*)ei;
        s = (int)p[i];
        d = (int)p[E + i];
    } else {
        const int* p = (const int*)ei;
        s = p[i];
        d = p[E + i];
    }
    s = min(max(s, 0), N - 1);
    d = min(max(d, 0), N - 1);
}

// ---------------- 1) count: deg[dst]++ (dst stream only) --------------------
__global__ void count_kernel(const void* __restrict__ ei,
                             int* __restrict__ deg, int* __restrict__ total,
                             int E, int N) {
    int is64 = detect_is64((const unsigned*)ei);
    if (blockIdx.x == 0 && threadIdx.x == 0) *total = 0;
    for (int i = blockIdx.x * blockDim.x + threadIdx.x; i < E;
         i += gridDim.x * blockDim.x) {
        int d;
        if (is64) d = (int)((const long long*)ei)[E + i];
        else      d = ((const int*)ei)[E + i];
        d = min(max(d, 0), N - 1);
        atomicAdd(&deg[d], 1);
    }
}

// ---------------- 2) GEMM (f32x2) + s epilogue + alloc tail -----------------
// 128 threads; block tile 128x64; thread tile 8 rows x 8 cols.
// f32x2 packs the two k-partials of one output: x pairs (k,k+1) are adjacent
// in row-major xs; W stored transposed (wsT[c][k]) so w pairs are adjacent.
// Row map rT+16i / col map cT+8j -> conflict-free 64-bit LDS (stride 132).
__global__ void __launch_bounds__(128, 2)
gemm_kernel(const float* __restrict__ x,
            const float* __restrict__ W,
            const float* __restrict__ a_src,
            const float* __restrict__ a_dst,
            float* __restrict__ Wh,
            float* __restrict__ ssrc,
            float* __restrict__ sdst,
            const int* __restrict__ deg,
            int* __restrict__ rowstart,
            int* __restrict__ total,
            int gemmBlocks, int N) {
    extern __shared__ float sm[];
    int tid = threadIdx.x;

    // ======== alloc tail path (unordered bucket allocation) ========
    if (blockIdx.x >= gemmBlocks) {
        __shared__ int warpsum[4];
        __shared__ int blockbase;
        int i = (blockIdx.x - gemmBlocks) * 128 + tid;
        int lane = tid & 31;
        int wid = tid >> 5;
        int v = (i < N) ? deg[i] : 0;
        int sc = v;
#pragma unroll
        for (int o = 1; o < 32; o <<= 1) {
            int t = __shfl_up_sync(0xFFFFFFFFu, sc, o);
            if (lane >= o) sc += t;
        }
        if (lane == 31) warpsum[wid] = sc;
        __syncthreads();
        if (tid < 4) {
            int ws = warpsum[tid];
            int s2 = ws;
#pragma unroll
            for (int o = 1; o < 4; o <<= 1) {
                int t = __shfl_up_sync(0xFu, s2, o);
                if (tid >= o) s2 += t;
            }
            warpsum[tid] = s2 - ws;
            if (tid == 3) blockbase = atomicAdd(total, s2);
        }
        __syncthreads();
        if (i < N) rowstart[i] = blockbase + warpsum[wid] + (sc - v);
        return;
    }

    // ======== GEMM path ========
    float* xs = sm;                   // [128][PADK]
    float* ws = sm + 128 * PADK;      // wsT [64][PADK]

    int r0 = blockIdx.x * 128;
    const float4* x4 = (const float4*)x;
#pragma unroll
    for (int t = 0; t < 32; t++) {    // 4096 float4 = 128 rows x 32
        int idx = tid + t * 128;
        int row = idx >> 5;
        int kq = idx & 31;
        int g = r0 + row;
        float4 v = make_float4(0.f, 0.f, 0.f, 0.f);
        if (g < N) v = x4[(size_t)g * 32 + kq];
        *(float4*)&xs[row * PADK + kq * 4] = v;
    }
    // W transpose into smem: wsT[c][k] = W[k][c]
#pragma unroll
    for (int t = 0; t < 64; t++) {    // 8192 floats
        int idx = tid + t * 128;
        int k = idx >> 6;
        int c = idx & 63;
        ws[c * PADK + k] = W[idx];
    }
    __syncthreads();

    int rT = tid >> 3;   // 0..15
    int cT = tid & 7;    // 0..7

    unsigned long long acc[8][8];
#pragma unroll
    for (int i = 0; i < 8; i++)
#pragma unroll
        for (int j = 0; j < 8; j++) acc[i][j] = 0ull;

#pragma unroll 2
    for (int k2 = 0; k2 < 64; k2++) {
        unsigned long long xv[8], wv[8];
#pragma unroll
        for (int i = 0; i < 8; i++)
            xv[i] = *(const unsigned long long*)&xs[(rT + 16 * i) * PADK + 2 * k2];
#pragma unroll
        for (int j = 0; j < 8; j++)
            wv[j] = *(const unsigned long long*)&ws[(cT + 8 * j) * PADK + 2 * k2];
#pragma unroll
        for (int i = 0; i < 8; i++)
#pragma unroll
            for (int j = 0; j < 8; j++)
                FMA_F32X2(acc[i][j], xv[i], wv[j], acc[i][j]);
    }

    // stage outputs to smem (reuse xs region) for coalesced store + s dots
    __syncthreads();
    float* st = sm;                   // [128][PADS]
#pragma unroll
    for (int i = 0; i < 8; i++)
#pragma unroll
        for (int j = 0; j < 8; j++) {
            unsigned lo, hi;
            asm("mov.b64 {%0, %1}, %2;" : "=r"(lo), "=r"(hi) : "l"(acc[i][j]));
            st[(rT + 16 * i) * PADS + (cT + 8 * j)] =
                __uint_as_float(lo) + __uint_as_float(hi);
        }
    __syncthreads();

    // thread tid owns row tid: coalesced Wh store + fused s epilogue
    int g = r0 + tid;
    if (g < N) {
        const float4* as4 = (const float4*)a_src;
        const float4* ad4 = (const float4*)a_dst;
        float s1 = 0.f, s2 = 0.f;
#pragma unroll
        for (int q = 0; q < 16; q++) {
            float4 v = *(float4*)&st[tid * PADS + q * 4];
            *(float4*)&Wh[(size_t)g * FOUT + q * 4] = v;
            float4 av = __ldg(&as4[q]);
            float4 dv = __ldg(&ad4[q]);
            s1 += v.x * av.x + v.y * av.y + v.z * av.z + v.w * av.w;
            s2 += v.x * dv.x + v.y * dv.y + v.z * dv.z + v.w * dv.w;
        }
        ssrc[g] = s1;
        sdst[g] = s2;
    }
}

// ---------------- 3) fill: e = exp(leaky(l)) unshifted; bucket by dst -------
__global__ void fill_kernel(const void* __restrict__ ei,
                            const float* __restrict__ ssrc,
                            const float* __restrict__ sdst,
                            const int* __restrict__ rowstart,
                            int* __restrict__ cursor,
                            uint2* __restrict__ bkt, int E, int N) {
    int is64 = detect_is64((const unsigned*)ei);
    int i = blockIdx.x * blockDim.x + threadIdx.x;
    if (i >= E) return;
    int s, d;
    load_edge(ei, is64, E, i, N, s, d);
    float t = ssrc[s] + sdst[d];
    float l = t > 0.f ? t : NEG * t;
    float e = __expf(l);
    int pos = atomicAdd(&cursor[d], 1);
    bkt[rowstart[d] + pos] = make_uint2((unsigned)s, __float_as_uint(e));
}

// ---------------- 4) gather (fp32 Wh) + state cleanup -----------------------
// 8 threads/node; lane owns 8 cols = 2 x float4; 2-way unroll; fp32 accum.
__global__ void gather_kernel(const uint2* __restrict__ bkt,
                              const int* __restrict__ rowstart,
                              int* __restrict__ deg,
                              int* __restrict__ cursor,
                              const float* __restrict__ Wh,
                              float* __restrict__ out, int N) {
    int t = blockIdx.x * blockDim.x + threadIdx.x;
    int node = t >> 3;
    int l = t & 7;
    if (node >= N) return;
    int beg = rowstart[node];
    int dg  = deg[node];
    int end = beg + dg;

    float4 p0 = make_float4(0.f, 0.f, 0.f, 0.f);
    float4 p1 = make_float4(0.f, 0.f, 0.f, 0.f);
    float4 q0 = make_float4(0.f, 0.f, 0.f, 0.f);
    float4 q1 = make_float4(0.f, 0.f, 0.f, 0.f);
    float den0 = 0.f, den1 = 0.f;

    int j = beg;
    for (; j + 2 <= end; j += 2) {
        uint2 b0 = __ldg(&bkt[j]);
        uint2 b1 = __ldg(&bkt[j + 1]);
        const float4* w0 = (const float4*)&Wh[(size_t)b0.x * FOUT + l * 8];
        const float4* w1 = (const float4*)&Wh[(size_t)b1.x * FOUT + l * 8];
        float4 u0 = __ldg(w0);
        float4 u1 = __ldg(w0 + 1);
        float4 v0 = __ldg(w1);
        float4 v1 = __ldg(w1 + 1);
        float e0 = __uint_as_float(b0.y);
        float e1 = __uint_as_float(b1.y);
        den0 += e0;
        den1 += e1;
        p0.x = fmaf(e0, u0.x, p0.x); p0.y = fmaf(e0, u0.y, p0.y);
        p0.z = fmaf(e0, u0.z, p0.z); p0.w = fmaf(e0, u0.w, p0.w);
        p1.x = fmaf(e0, u1.x, p1.x); p1.y = fmaf(e0, u1.y, p1.y);
        p1.z = fmaf(e0, u1.z, p1.z); p1.w = fmaf(e0, u1.w, p1.w);
        q0.x = fmaf(e1, v0.x, q0.x); q0.y = fmaf(e1, v0.y, q0.y);
        q0.z = fmaf(e1, v0.z, q0.z); q0.w = fmaf(e1, v0.w, q0.w);
        q1.x = fmaf(e1, v1.x, q1.x); q1.y = fmaf(e1, v1.y, q1.y);
        q1.z = fmaf(e1, v1.z, q1.z); q1.w = fmaf(e1, v1.w, q1.w);
    }
    if (j < end) {
        uint2 b0 = __ldg(&bkt[j]);
        const float4* w0 = (const float4*)&Wh[(size_t)b0.x * FOUT + l * 8];
        float4 u0 = __ldg(w0);
        float4 u1 = __ldg(w0 + 1);
        float e0 = __uint_as_float(b0.y);
        den0 += e0;
        p0.x = fmaf(e0, u0.x, p0.x); p0.y = fmaf(e0, u0.y, p0.y);
        p0.z = fmaf(e0, u0.z, p0.z); p0.w = fmaf(e0, u0.w, p0.w);
        p1.x = fmaf(e0, u1.x, p1.x); p1.y = fmaf(e0, u1.y, p1.y);
        p1.z = fmaf(e0, u1.z, p1.z); p1.w = fmaf(e0, u1.w, p1.w);
    }

    float inv = __fdividef(1.f, den0 + den1 + 1e-16f);
    float r[8];
    r[0] = (p0.x + q0.x) * inv; r[1] = (p0.y + q0.y) * inv;
    r[2] = (p0.z + q0.z) * inv; r[3] = (p0.w + q0.w) * inv;
    r[4] = (p1.x + q1.x) * inv; r[5] = (p1.y + q1.y) * inv;
    r[6] = (p1.z + q1.z) * inv; r[7] = (p1.w + q1.w) * inv;
#pragma unroll
    for (int k = 0; k < 8; k++) r[k] = r[k] > 0.f ? r[k] : expm1f(r[k]);

    *(float4*)&out[(size_t)node * FOUT + l * 8] =
        make_float4(r[0], r[1], r[2], r[3]);
    *(float4*)&out[(size_t)node * FOUT + l * 8 + 4] =
        make_float4(r[4], r[5], r[6], r[7]);

    // cleanup for next invocation
    if (l == 0) deg[node] = 0;
    if (l == 1) cursor[node] = 0;
}

// ---------------- launch ----------------------------------------------------
extern "C" void kernel_launch(void* const* d_in, const int* in_sizes, int n_in,
                              void* d_out, int out_size) {
    const float* x = 0;
    const void*  ei = 0;
    const float* W = 0;
    const float* a_src = 0;
    const float* a_dst = 0;
    int x_sz = 0, ei_sz = 0;

    for (int i = 0; i < n_in; i++) {
        int sz = in_sizes[i];
        if (sz == 64) {
            if (!a_src) a_src = (const float*)d_in[i];
            else        a_dst = (const float*)d_in[i];
        } else if (sz == FIN * FOUT) {
            W = (const float*)d_in[i];
        } else if (sz > x_sz) {
            ei = (const void*)x; ei_sz = x_sz;
            x = (const float*)d_in[i]; x_sz = sz;
        } else {
            ei = (const void*)d_in[i]; ei_sz = sz;
        }
    }

    float* out = (float*)d_out;
    int N = x_sz / FIN;
    int E = ei_sz / 2;

    void *pWh, *pss, *psd, *pdeg, *pcur, *prow, *pbkt, *ptot;
    cudaGetSymbolAddress(&pWh, g_Wh);
    cudaGetSymbolAddress(&pss, g_ssrc);
    cudaGetSymbolAddress(&psd, g_sdst);
    cudaGetSymbolAddress(&pdeg, g_deg);
    cudaGetSymbolAddress(&pcur, g_cursor);
    cudaGetSymbolAddress(&prow, g_rowstart);
    cudaGetSymbolAddress(&pbkt, g_bkt);
    cudaGetSymbolAddress(&ptot, g_total);

    count_kernel<<<1184, 256>>>(ei, (int*)pdeg, (int*)ptot, E, N);

    int gemmBlocks  = (N + 127) / 128;
    int allocBlocks = (N + 127) / 128;
    int smemBytes = (128 * PADK + 64 * PADK) * 4;   // 101,376 B
    cudaFuncSetAttribute(gemm_kernel,
                         cudaFuncAttributeMaxDynamicSharedMemorySize, smemBytes);
    gemm_kernel<<<gemmBlocks + allocBlocks, 128, smemBytes>>>(
        x, W, a_src, a_dst, (float*)pWh, (float*)pss, (float*)psd,
        (int*)pdeg, (int*)prow, (int*)ptot, gemmBlocks, N);

    fill_kernel<<<(E + 255) / 256, 256>>>(ei, (float*)pss, (float*)psd,
                                          (int*)prow, (int*)pcur,
                                          (uint2*)pbkt, E, N);

    long long gthreads = (long long)N * 8;
    gather_kernel<<<(int)((gthreads + 255) / 256), 256>>>(
        (uint2*)pbkt, (int*)prow, (int*)pdeg, (int*)pcur,
        (const float*)pWh, out, N);
}

// round 16
// speedup vs baseline: 1.0528x; 1.0528x over previous
#include <cuda_runtime.h>
#include <cuda_fp16.h>
#include <cstdint>
#include <float.h>

#define FIN  128
#define FOUT 64
#define NEG  0.2f
#define NMAX 50048
#define EMAX 1000192

// ---------------- scratch (device globals; zero-initialized at load) --------
// Invariant: deg[], cursor[] are zero at entry; restored by gather epilogue.
__device__ __half   g_Whh[NMAX * FOUT];   // fp16 Wh (gather-only consumer)
__device__ float    g_ssrc[NMAX];
__device__ float    g_sdst[NMAX];
__device__ int      g_deg[NMAX];
__device__ int      g_cursor[NMAX];
__device__ int      g_rowstart[NMAX];
__device__ uint2    g_bkt[EMAX];          // (src, bitcast(e)) bucketed by dst
__device__ int      g_total;              // bump allocator

// ---------------- per-block edge-dtype detect --------------------------------
__device__ __forceinline__ int detect_is64(const unsigned* eiw) {
    unsigned v = 0;
    if (threadIdx.x < 64) v = eiw[threadIdx.x * 2 + 1];
    return __syncthreads_or(v != 0u) ? 0 : 1;
}

__device__ __forceinline__ void load_edge(const void* ei, int is64, int E,
                                          int i, int N, int& s, int& d) {
    if (is64) {
        const long long* p = (const long long*)ei;
        s = (int)p[i];
        d = (int)p[E + i];
    } else {
        const int* p = (const int*)ei;
        s = p[i];
        d = p[E + i];
    }
    s = min(max(s, 0), N - 1);
    d = min(max(d, 0), N - 1);
}

// ---------------- 1) count: deg[dst]++ (dst stream only) --------------------
__global__ void count_kernel(const void* __restrict__ ei,
                             int* __restrict__ deg, int* __restrict__ total,
                             int E, int N) {
    int is64 = detect_is64((const unsigned*)ei);
    if (blockIdx.x == 0 && threadIdx.x == 0) *total = 0;
    for (int i = blockIdx.x * blockDim.x + threadIdx.x; i < E;
         i += gridDim.x * blockDim.x) {
        int d;
        if (is64) d = (int)((const long long*)ei)[E + i];
        else      d = ((const int*)ei)[E + i];
        d = min(max(d, 0), N - 1);
        atomicAdd(&deg[d], 1);
    }
}

// ---------------- 2) GEMM + s epilogue + alloc tail blocks ------------------
__global__ void gemm_kernel(const float* __restrict__ x,
                            const float* __restrict__ W,
                            const float* __restrict__ a_src,
                            const float* __restrict__ a_dst,
                            __half* __restrict__ Whh,
                            float* __restrict__ ssrc,
                            float* __restrict__ sdst,
                            const int* __restrict__ deg,
                            int* __restrict__ rowstart,
                            int* __restrict__ total,
                            int gemmBlocks, int N) {
    extern __shared__ float sm[];
    int tid = threadIdx.x;

    // ======== alloc tail path (unordered bucket allocation) ========
    if (blockIdx.x >= gemmBlocks) {
        int* warpsum = (int*)sm;          // 8 ints
        int* blockbase = (int*)sm + 8;    // 1 int
        int i = (blockIdx.x - gemmBlocks) * blockDim.x + tid;
        int lane = tid & 31;
        int wid = tid >> 5;

        int v = (i < N) ? deg[i] : 0;
        int sc = v;
#pragma unroll
        for (int o = 1; o < 32; o <<= 1) {
            int t = __shfl_up_sync(0xFFFFFFFFu, sc, o);
            if (lane >= o) sc += t;
        }
        if (lane == 31) warpsum[wid] = sc;
        __syncthreads();
        if (tid < 8) {
            int ws = warpsum[tid];
            int s2 = ws;
#pragma unroll
            for (int o = 1; o < 8; o <<= 1) {
                int t = __shfl_up_sync(0xFFu, s2, o);
                if (tid >= o) s2 += t;
            }
            warpsum[tid] = s2 - ws;
            if (tid == 7) *blockbase = atomicAdd(total, s2);
        }
        __syncthreads();
        if (i < N) rowstart[i] = *blockbase + warpsum[wid] + (sc - v);
        return;
    }

    // ======== GEMM path ========
    float* xs = sm;              // 128*128
    float* ws = sm + 128 * 128;  // 128*64

    const float4* W4 = (const float4*)W;
    float4* ws4 = (float4*)ws;
#pragma unroll
    for (int i = 0; i < 8; i++) ws4[tid + i * 256] = W4[tid + i * 256];

    int r0 = blockIdx.x * 128;
    const float4* x4 = (const float4*)x;
    float4* xs4 = (float4*)xs;
#pragma unroll
    for (int i = 0; i < 16; i++) {
        int idx = tid + i * 256;
        int row = idx >> 5;
        int g = r0 + row;
        float4 v = make_float4(0.f, 0.f, 0.f, 0.f);
        if (g < N) v = x4[(size_t)g * 32 + (idx & 31)];
        xs4[idx] = v;
    }
    __syncthreads();

    int t16 = tid & 15;
    int colBase = t16 * 4;
    int rowBase = (tid >> 4) * 8;

    float acc[8][4];
#pragma unroll
    for (int i = 0; i < 8; i++)
#pragma unroll
        for (int j = 0; j < 4; j++) acc[i][j] = 0.f;

#pragma unroll 4
    for (int k4 = 0; k4 < 32; k4++) {
        float4 w0 = *(float4*)&ws[(k4 * 4 + 0) * 64 + colBase];
        float4 w1 = *(float4*)&ws[(k4 * 4 + 1) * 64 + colBase];
        float4 w2 = *(float4*)&ws[(k4 * 4 + 2) * 64 + colBase];
        float4 w3 = *(float4*)&ws[(k4 * 4 + 3) * 64 + colBase];
#pragma unroll
        for (int i = 0; i < 8; i++) {
            float4 xv = *(float4*)&xs[(rowBase + i) * 128 + k4 * 4];
            acc[i][0] += xv.x * w0.x + xv.y * w1.x + xv.z * w2.x + xv.w * w3.x;
            acc[i][1] += xv.x * w0.y + xv.y * w1.y + xv.z * w2.y + xv.w * w3.y;
            acc[i][2] += xv.x * w0.z + xv.y * w1.z + xv.z * w2.z + xv.w * w3.z;
            acc[i][3] += xv.x * w0.w + xv.y * w1.w + xv.z * w2.w + xv.w * w3.w;
        }
    }

    // fp16 store of Wh
#pragma unroll
    for (int i = 0; i < 8; i++) {
        int g = r0 + rowBase + i;
        if (g < N) {
            __half2 h0 = __float22half2_rn(make_float2(acc[i][0], acc[i][1]));
            __half2 h1 = __float22half2_rn(make_float2(acc[i][2], acc[i][3]));
            uint2 pk = make_uint2(*(unsigned*)&h0, *(unsigned*)&h1);
            *(uint2*)&Whh[(size_t)g * FOUT + colBase] = pk;
        }
    }

    // fused s epilogue (fp32 accumulators)
    float4 asv = *(const float4*)&a_src[colBase];
    float4 adv = *(const float4*)&a_dst[colBase];

    __syncthreads();
    float* ps = sm;                // 128*17
    float* pd = sm + 128 * 17;     // 128*17
#pragma unroll
    for (int i = 0; i < 8; i++) {
        int row = rowBase + i;
        float vs = acc[i][0] * asv.x + acc[i][1] * asv.y +
                   acc[i][2] * asv.z + acc[i][3] * asv.w;
        float vd = acc[i][0] * adv.x + acc[i][1] * adv.y +
                   acc[i][2] * adv.z + acc[i][3] * adv.w;
        ps[row * 17 + t16] = vs;
        pd[row * 17 + t16] = vd;
    }
    __syncthreads();
    if (tid < 128) {
        float s1 = 0.f, s2 = 0.f;
#pragma unroll
        for (int k = 0; k < 16; k++) {
            s1 += ps[tid * 17 + k];
            s2 += pd[tid * 17 + k];
        }
        int g = r0 + tid;
        if (g < N) { ssrc[g] = s1; sdst[g] = s2; }
    }
}

// ---------------- 3) fill: e = exp(leaky(l)) unshifted; bucket by dst -------
__global__ void fill_kernel(const void* __restrict__ ei,
                            const float* __restrict__ ssrc,
                            const float* __restrict__ sdst,
                            const int* __restrict__ rowstart,
                            int* __restrict__ cursor,
                            uint2* __restrict__ bkt, int E, int N) {
    int is64 = detect_is64((const unsigned*)ei);
    int i = blockIdx.x * blockDim.x + threadIdx.x;
    if (i >= E) return;
    int s, d;
    load_edge(ei, is64, E, i, N, s, d);
    float t = ssrc[s] + sdst[d];
    float l = t > 0.f ? t : NEG * t;
    float e = __expf(l);
    int pos = atomicAdd(&cursor[d], 1);
    bkt[rowstart[d] + pos] = make_uint2((unsigned)s, __float_as_uint(e));
}

// ---------------- 4) gather: warp-per-node + state cleanup ------------------
// One warp per node; lane owns one half2 column pair (4B). Per edge: one
// broadcast bkt load + one coalesced 128B row load; no divergence waste, no
// shuffles (denom computed redundantly per-lane). 4-way unroll for MLP.
__global__ void gather_kernel(const uint2* __restrict__ bkt,
                              const int* __restrict__ rowstart,
                              int* __restrict__ deg,
                              int* __restrict__ cursor,
                              const __half* __restrict__ Whh,
                              float* __restrict__ out, int N) {
    int warp = (blockIdx.x * blockDim.x + threadIdx.x) >> 5;
    int lane = threadIdx.x & 31;
    if (warp >= N) return;
    int beg = rowstart[warp];
    int dg  = deg[warp];
    int end = beg + dg;

    float2 a0 = make_float2(0.f, 0.f);
    float2 a1 = make_float2(0.f, 0.f);
    float2 a2 = make_float2(0.f, 0.f);
    float2 a3 = make_float2(0.f, 0.f);
    float den0 = 0.f, den1 = 0.f, den2 = 0.f, den3 = 0.f;

    int j = beg;
    for (; j + 4 <= end; j += 4) {
        uint2 b0 = __ldg(&bkt[j]);
        uint2 b1 = __ldg(&bkt[j + 1]);
        uint2 b2 = __ldg(&bkt[j + 2]);
        uint2 b3 = __ldg(&bkt[j + 3]);
        __half2 h0 = *(const __half2*)&Whh[(size_t)b0.x * FOUT + lane * 2];
        __half2 h1 = *(const __half2*)&Whh[(size_t)b1.x * FOUT + lane * 2];
        __half2 h2 = *(const __half2*)&Whh[(size_t)b2.x * FOUT + lane * 2];
        __half2 h3 = *(const __half2*)&Whh[(size_t)b3.x * FOUT + lane * 2];
        float e0 = __uint_as_float(b0.y);
        float e1 = __uint_as_float(b1.y);
        float e2 = __uint_as_float(b2.y);
        float e3 = __uint_as_float(b3.y);
        den0 += e0; den1 += e1; den2 += e2; den3 += e3;
        float2 f0 = __half22float2(h0);
        float2 f1 = __half22float2(h1);
        float2 f2 = __half22float2(h2);
        float2 f3 = __half22float2(h3);
        a0.x = fmaf(e0, f0.x, a0.x); a0.y = fmaf(e0, f0.y, a0.y);
        a1.x = fmaf(e1, f1.x, a1.x); a1.y = fmaf(e1, f1.y, a1.y);
        a2.x = fmaf(e2, f2.x, a2.x); a2.y = fmaf(e2, f2.y, a2.y);
        a3.x = fmaf(e3, f3.x, a3.x); a3.y = fmaf(e3, f3.y, a3.y);
    }
    for (; j < end; j++) {
        uint2 b0 = __ldg(&bkt[j]);
        __half2 h0 = *(const __half2*)&Whh[(size_t)b0.x * FOUT + lane * 2];
        float e0 = __uint_as_float(b0.y);
        den0 += e0;
        float2 f0 = __half22float2(h0);
        a0.x = fmaf(e0, f0.x, a0.x); a0.y = fmaf(e0, f0.y, a0.y);
    }

    float denom = (den0 + den1) + (den2 + den3);
    float inv = __fdividef(1.f, denom + 1e-16f);
    float vx = ((a0.x + a1.x) + (a2.x + a3.x)) * inv;
    float vy = ((a0.y + a1.y) + (a2.y + a3.y)) * inv;
    vx = vx > 0.f ? vx : expm1f(vx);
    vy = vy > 0.f ? vy : expm1f(vy);
    *(float2*)&out[(size_t)warp * FOUT + lane * 2] = make_float2(vx, vy);

    // cleanup for next invocation
    if (lane == 0) deg[warp] = 0;
    if (lane == 1) cursor[warp] = 0;
}

// ---------------- launch ----------------------------------------------------
extern "C" void kernel_launch(void* const* d_in, const int* in_sizes, int n_in,
                              void* d_out, int out_size) {
    const float* x = 0;
    const void*  ei = 0;
    const float* W = 0;
    const float* a_src = 0;
    const float* a_dst = 0;
    int x_sz = 0, ei_sz = 0;

    for (int i = 0; i < n_in; i++) {
        int sz = in_sizes[i];
        if (sz == 64) {
            if (!a_src) a_src = (const float*)d_in[i];
            else        a_dst = (const float*)d_in[i];
        } else if (sz == FIN * FOUT) {
            W = (const float*)d_in[i];
        } else if (sz > x_sz) {
            ei = (const void*)x; ei_sz = x_sz;
            x = (const float*)d_in[i]; x_sz = sz;
        } else {
            ei = (const void*)d_in[i]; ei_sz = sz;
        }
    }

    float* out = (float*)d_out;
    int N = x_sz / FIN;
    int E = ei_sz / 2;

    void *pWhh, *pss, *psd, *pdeg, *pcur, *prow, *pbkt, *ptot;
    cudaGetSymbolAddress(&pWhh, g_Whh);
    cudaGetSymbolAddress(&pss, g_ssrc);
    cudaGetSymbolAddress(&psd, g_sdst);
    cudaGetSymbolAddress(&pdeg, g_deg);
    cudaGetSymbolAddress(&pcur, g_cursor);
    cudaGetSymbolAddress(&prow, g_rowstart);
    cudaGetSymbolAddress(&pbkt, g_bkt);
    cudaGetSymbolAddress(&ptot, g_total);

    count_kernel<<<1184, 256>>>(ei, (int*)pdeg, (int*)ptot, E, N);

    int gemmBlocks = (N + 127) / 128;
    int allocBlocks = (N + 255) / 256;
    cudaFuncSetAttribute(gemm_kernel,
                         cudaFuncAttributeMaxDynamicSharedMemorySize, 96 * 1024);
    gemm_kernel<<<gemmBlocks + allocBlocks, 256, 96 * 1024>>>(
        x, W, a_src, a_dst, (__half*)pWhh, (float*)pss, (float*)psd,
        (int*)pdeg, (int*)prow, (int*)ptot, gemmBlocks, N);

    fill_kernel<<<(E + 255) / 256, 256>>>(ei, (float*)pss, (float*)psd,
                                          (int*)prow, (int*)pcur,
                                          (uint2*)pbkt, E, N);

    long long gthreads = (long long)N * 32;
    gather_kernel<<<(int)((gthreads + 255) / 256), 256>>>(
        (uint2*)pbkt, (int*)prow, (int*)pdeg, (int*)pcur,
        (const __half*)pWhh, out, N);
}